// round 3
// baseline (speedup 1.0000x reference)
#include <cuda_runtime.h>

#define NB 16
#define NPTS 4096
#define NP 512
#define NS 32
#define MROWS (NB*NP*NS)   // 262144 rows
#define SEGS 16

typedef unsigned long long u64;
typedef unsigned int u32;

// ---------------- scratch ----------------
__device__ float g_newxyz[NB*NP*3];
__device__ unsigned int g_prog[NB];
__device__ float g_h0[9*MROWS];
__device__ float g_h1[64*MROWS];
__device__ float g_h2[64*MROWS];
__device__ float g_h3[128*MROWS];
__device__ float2 g_part[128*SEGS];
__device__ float g_a1[64], g_c1[64];
__device__ float g_a2[64], g_c2[64];
__device__ float g_a3[128], g_c3[128];

// ---------------- helpers ----------------
__device__ __forceinline__ u64 pk(float lo, float hi) {
    u64 r; asm("mov.b64 %0,{%1,%2};" : "=l"(r) : "f"(lo), "f"(hi)); return r;
}
__device__ __forceinline__ void upk(u64 v, float& lo, float& hi) {
    asm("mov.b64 {%0,%1},%2;" : "=f"(lo), "=f"(hi) : "l"(v));
}
__device__ __forceinline__ u64 addx2(u64 a, u64 b) {
    u64 r; asm("add.rn.f32x2 %0,%1,%2;" : "=l"(r) : "l"(a), "l"(b)); return r;
}
__device__ __forceinline__ u64 mulx2(u64 a, u64 b) {
    u64 r; asm("mul.rn.f32x2 %0,%1,%2;" : "=l"(r) : "l"(a), "l"(b)); return r;
}
__device__ __forceinline__ u32 rmaxu(u32 v) {
    u32 r; asm("redux.sync.max.u32 %0,%1,0xffffffff;" : "=r"(r) : "r"(v)); return r;
}
__device__ __forceinline__ u32 rminu(u32 v) {
    u32 r; asm("redux.sync.min.u32 %0,%1,0xffffffff;" : "=r"(r) : "r"(v)); return r;
}
__device__ __forceinline__ u32 f2ord(float f) {
    u32 b = __float_as_uint(f);
    return b ^ (0x80000000u | (u32)((int)b >> 31));
}

// =======================================================================
// init: reset progress counters (every replay)
// =======================================================================
__global__ void init_kernel() {
    if (threadIdx.x < NB) g_prog[threadIdx.x] = 0u;
}

// =======================================================================
// FPS body: one block per batch, 256 thr x 16 pts. Publishes centroids
// progressively with release semantics.
// =======================================================================
__device__ void fps_body(int b, const float* __restrict__ xyz,
                         float* __restrict__ out0, float* fsm) {
    float* sx = fsm;
    float* sy = fsm + NPTS;
    float* sz = fsm + 2 * NPTS;
    u64* rw = (u64*)(fsm + 3 * NPTS);   // [2][8]

    const int tid = threadIdx.x, wid = tid >> 5, lid = tid & 31;
    const float* base = xyz + (size_t)b * 3 * NPTS;

    u64 xp[8], yp[8], zp[8];
    float dist[16];
#pragma unroll
    for (int k = 0; k < 8; k++) {
        int n0 = tid + 256 * (2 * k), n1 = n0 + 256;
        float x0 = base[n0], x1 = base[n1];
        float y0 = base[NPTS + n0], y1 = base[NPTS + n1];
        float z0 = base[2 * NPTS + n0], z1 = base[2 * NPTS + n1];
        xp[k] = pk(x0, x1); yp[k] = pk(y0, y1); zp[k] = pk(z0, z1);
        sx[n0] = x0; sx[n1] = x1;
        sy[n0] = y0; sy[n1] = y1;
        sz[n0] = z0; sz[n1] = z1;
        dist[2 * k] = 1e10f; dist[2 * k + 1] = 1e10f;
    }
    float cx = base[0], cy = base[NPTS], cz = base[2 * NPTS];
    __syncthreads();

    for (int it = 0; it < NP; it++) {
        if (tid == 0) {
            g_newxyz[((size_t)b * NP + it) * 3 + 0] = cx;
            g_newxyz[((size_t)b * NP + it) * 3 + 1] = cy;
            g_newxyz[((size_t)b * NP + it) * 3 + 2] = cz;
            out0[((size_t)b * 3 + 0) * NP + it] = cx;
            out0[((size_t)b * 3 + 1) * NP + it] = cy;
            out0[((size_t)b * 3 + 2) * NP + it] = cz;
            asm volatile("st.release.gpu.global.u32 [%0], %1;"
                         :: "l"(&g_prog[b]), "r"((u32)(it + 1)) : "memory");
        }
        u64 ncx = pk(-cx, -cx), ncy = pk(-cy, -cy), ncz = pk(-cz, -cz);
        float bd = -1.0f;
#pragma unroll
        for (int k = 0; k < 8; k++) {
            u64 dx = addx2(xp[k], ncx);
            u64 dy = addx2(yp[k], ncy);
            u64 dz = addx2(zp[k], ncz);
            u64 d2 = addx2(addx2(mulx2(dx, dx), mulx2(dy, dy)), mulx2(dz, dz));
            float lo, hi; upk(d2, lo, hi);
            dist[2 * k] = fminf(dist[2 * k], lo);
            dist[2 * k + 1] = fminf(dist[2 * k + 1], hi);
            bd = fmaxf(bd, fmaxf(dist[2 * k], dist[2 * k + 1]));
        }
        int bj = 0;
#pragma unroll
        for (int j = 15; j >= 0; j--) if (dist[j] == bd) bj = j;  // smallest j
        u32 bi = (u32)(tid + 256 * bj);
        u32 bb = __float_as_uint(bd);
        u32 m = rmaxu(bb);
        u32 cand = (bb == m) ? bi : 0xffffffffu;
        u32 pmin = rminu(cand);
        int par = it & 1;
        if (lid == 0) rw[par * 8 + wid] = ((u64)m << 32) | (u32)(NPTS - 1 - pmin);
        __syncthreads();
        u64 kk = rw[par * 8 + (lid & 7)];
        u32 hi2 = (u32)(kk >> 32);
        u32 m2 = rmaxu(hi2);
        u32 c2 = (hi2 == m2) ? (u32)kk : 0u;
        u32 inv = rmaxu(c2);
        int widx = NPTS - 1 - (int)inv;
        cx = sx[widx]; cy = sy[widx]; cz = sz[widx];
    }
}

// =======================================================================
// Ball body: one block per query. Keys in SMEM (no local-mem spill),
// redux-based extraction, spins until its centroid is published.
// =======================================================================
__device__ void ball_body(int q, const float* __restrict__ xyz,
                          const float* __restrict__ points, float* fsm) {
    u64* sk = (u64*)fsm;                 // [16][256]
    u64* rw = (u64*)(fsm + 3 * NPTS);    // [2][8]
    const int tid = threadIdx.x, wid = tid >> 5, lid = tid & 31;
    const int b = q >> 9, s = q & 511;
    const float* base = xyz + (size_t)b * 3 * NPTS;

    u64 xp[8], yp[8], zp[8], pnp[8];
#pragma unroll
    for (int k = 0; k < 8; k++) {
        int n0 = tid + 256 * (2 * k), n1 = n0 + 256;
        float x0 = base[n0], x1 = base[n1];
        float y0 = base[NPTS + n0], y1 = base[NPTS + n1];
        float z0 = base[2 * NPTS + n0], z1 = base[2 * NPTS + n1];
        xp[k] = pk(x0, x1); yp[k] = pk(y0, y1); zp[k] = pk(z0, z1);
        pnp[k] = addx2(addx2(mulx2(xp[k], xp[k]), mulx2(yp[k], yp[k])),
                       mulx2(zp[k], zp[k]));
    }

    if (tid == 0) {
        u32 p;
        while (true) {
            asm volatile("ld.acquire.gpu.global.u32 %0,[%1];"
                         : "=r"(p) : "l"(&g_prog[b]) : "memory");
            if (p > (u32)s) break;
            __nanosleep(128);
        }
    }
    __syncthreads();

    const float qx = g_newxyz[(size_t)q * 3 + 0];
    const float qy = g_newxyz[(size_t)q * 3 + 1];
    const float qz = g_newxyz[(size_t)q * 3 + 2];
    const float qn = __fadd_rn(__fadd_rn(__fmul_rn(qx, qx), __fmul_rn(qy, qy)),
                               __fmul_rn(qz, qz));
    u64 qxp = pk(qx, qx), qyp = pk(qy, qy), qzp = pk(qz, qz);
    u64 qnp = pk(qn, qn), n2p = pk(-2.0f, -2.0f);

    u64 loc = ~0ull;
#pragma unroll
    for (int k = 0; k < 8; k++) {
        u64 dt = addx2(addx2(mulx2(xp[k], qxp), mulx2(yp[k], qyp)),
                       mulx2(zp[k], qzp));
        u64 d = addx2(addx2(qnp, pnp[k]), mulx2(dt, n2p));
        float lo, hi; upk(d, lo, hi);
        int n0 = tid + 256 * (2 * k);
        u64 k0 = ((u64)f2ord(lo) << 32) | (u32)n0;
        u64 k1 = ((u64)f2ord(hi) << 32) | (u32)(n0 + 256);
        sk[(size_t)(2 * k) * 256 + tid] = k0;
        sk[(size_t)(2 * k + 1) * 256 + tid] = k1;
        u64 mn = (k0 < k1) ? k0 : k1;
        loc = (mn < loc) ? mn : loc;
    }

    u32 first_n = 0, wd = 0, wn = 0;
    for (int k = 0; k < NS; k++) {
        u32 hi = (u32)(loc >> 32);
        u32 m = rminu(hi);
        u32 cand = (hi == m) ? (u32)loc : 0xffffffffu;
        u32 nw = rminu(cand);
        int par = k & 1;
        if (lid == 0) rw[par * 8 + wid] = ((u64)m << 32) | nw;
        __syncthreads();
        u64 kk = rw[par * 8 + (lid & 7)];
        u32 h2 = (u32)(kk >> 32);
        u32 m2v = rminu(h2);
        u32 c2 = (h2 == m2v) ? (u32)kk : 0xffffffffu;
        u32 nmin = rminu(c2);
        if (k == 0) first_n = nmin;
        if (tid == k) { wd = m2v; wn = nmin; }
        if ((nmin & 255u) == (u32)tid) {
            sk[(size_t)(nmin >> 8) * 256 + tid] = ~0ull;
            u64 l = sk[tid];
#pragma unroll
            for (int j = 1; j < 16; j++) {
                u64 v = sk[(size_t)j * 256 + tid];
                l = (v < l) ? v : l;
            }
            loc = l;
        }
    }

    if (tid < NS) {
        const u32 uth = f2ord(0.04f);  // radius^2
        u32 idx = (wd > uth) ? first_n : wn;
        size_t row = (size_t)q * NS + tid;
        float x = base[idx], y = base[NPTS + idx], z = base[2 * NPTS + idx];
        g_h0[0 * (size_t)MROWS + row] = x - qx;
        g_h0[1 * (size_t)MROWS + row] = y - qy;
        g_h0[2 * (size_t)MROWS + row] = z - qz;
        const float* pb = points + (size_t)b * 6 * NPTS;
#pragma unroll
        for (int d = 0; d < 6; d++)
            g_h0[(size_t)(3 + d) * MROWS + row] = pb[(size_t)d * NPTS + idx];
    }
}

// fused kernel: blocks 0..15 = FPS, 16..8207 = ball queries
__global__ void __launch_bounds__(256) fused_fps_ball(const float* __restrict__ xyz,
                                                      const float* __restrict__ points,
                                                      float* __restrict__ out0) {
    extern __shared__ float fsm[];
    if (blockIdx.x < NB) fps_body(blockIdx.x, xyz, out0, fsm);
    else                 ball_body(blockIdx.x - NB, xyz, points, fsm);
}

// =======================================================================
// Stage 3: pointwise MLP via packed f32x2 FMA (2 output channels / instr).
// =======================================================================
__device__ __forceinline__ void fma2(u64& acc, u64 w, u64 x) {
    asm("fma.rn.f32x2 %0, %1, %2, %0;" : "+l"(acc) : "l"(w), "l"(x));
}

template <int IC, bool BN>
__global__ void __launch_bounds__(256) mlp_kernel(const float* __restrict__ in,
                                                  const float* __restrict__ W,
                                                  const float* __restrict__ bias,
                                                  const float* __restrict__ aP,
                                                  const float* __restrict__ cP,
                                                  float* __restrict__ out) {
    __shared__ __align__(16) float Wsh[IC][64];
    __shared__ float bsh[64];
    __shared__ float ash[IC], csh[IC];
    const int tid = threadIdx.x;
    const int ocb = blockIdx.y * 64;

    for (int i = tid; i < IC * 64; i += 256) {
        int c = i >> 6, o = i & 63;
        Wsh[c][o] = W[(size_t)(ocb + o) * IC + c];
    }
    if (tid < 64) bsh[tid] = bias[ocb + tid];
    if (BN) {
        for (int c = tid; c < IC; c += 256) { ash[c] = aP[c]; csh[c] = cP[c]; }
    }
    __syncthreads();

    const size_t r = (size_t)blockIdx.x * 256 + tid;
    const float* inr = in + r;

    u64 acc[32];
#pragma unroll
    for (int k = 0; k < 32; k++)
        asm("mov.b64 %0, {%1, %2};" : "=l"(acc[k]) : "f"(bsh[2 * k]), "f"(bsh[2 * k + 1]));

#pragma unroll 8
    for (int c = 0; c < IC; c++) {
        float x = inr[(size_t)c * MROWS];
        if (BN) x = fmaxf(fmaf(ash[c], x, csh[c]), 0.0f);
        u64 x2;
        asm("mov.b64 %0, {%1, %1};" : "=l"(x2) : "f"(x));
        const ulonglong2* w4 = reinterpret_cast<const ulonglong2*>(&Wsh[c][0]);
#pragma unroll
        for (int k4 = 0; k4 < 16; k4++) {
            ulonglong2 w = w4[k4];
            fma2(acc[2 * k4 + 0], w.x, x2);
            fma2(acc[2 * k4 + 1], w.y, x2);
        }
    }
    float* outr = out + (size_t)ocb * MROWS + r;
#pragma unroll
    for (int k = 0; k < 32; k++) {
        float lo, hi;
        asm("mov.b64 {%0, %1}, %2;" : "=f"(lo), "=f"(hi) : "l"(acc[k]));
        outr[(size_t)(2 * k) * MROWS] = lo;
        outr[(size_t)(2 * k + 1) * MROWS] = hi;
    }
}

// =======================================================================
// BN stats: partial sums over (nch x SEGS) grid, then tiny double combine.
// =======================================================================
__global__ void __launch_bounds__(256) coeffp_kernel(const float* __restrict__ h,
                                                     float2* __restrict__ part) {
    const int ch = blockIdx.x, seg = blockIdx.y, tid = threadIdx.x;
    const float4* p = reinterpret_cast<const float4*>(
        h + (size_t)ch * MROWS + (size_t)seg * (MROWS / SEGS));
    float s = 0.f, s2 = 0.f;
#pragma unroll 4
    for (int i = tid; i < MROWS / SEGS / 4; i += 256) {
        float4 v = p[i];
        s += ((v.x + v.y) + (v.z + v.w));
        s2 += ((v.x * v.x + v.y * v.y) + (v.z * v.z + v.w * v.w));
    }
    __shared__ float sh[256], sh2[256];
    sh[tid] = s; sh2[tid] = s2;
    __syncthreads();
    for (int off = 128; off > 0; off >>= 1) {
        if (tid < off) { sh[tid] += sh[tid + off]; sh2[tid] += sh2[tid + off]; }
        __syncthreads();
    }
    if (tid == 0) part[ch * SEGS + seg] = make_float2(sh[0], sh2[0]);
}

__global__ void comb_kernel(const float2* __restrict__ part,
                            const float* __restrict__ g,
                            const float* __restrict__ be,
                            float* __restrict__ a, float* __restrict__ c, int nch) {
    int ch = threadIdx.x;
    if (ch >= nch) return;
    double s = 0.0, s2 = 0.0;
    for (int i = 0; i < SEGS; i++) {
        float2 p = part[ch * SEGS + i];
        s += (double)p.x; s2 += (double)p.y;
    }
    double mean = s / (double)MROWS;
    double var = s2 / (double)MROWS - mean * mean;
    double af = (double)g[ch] / sqrt(var + 1e-5);
    a[ch] = (float)af;
    c[ch] = (float)((double)be[ch] - mean * af);
}

// =======================================================================
// Pool: warp per query, lanes = 32 samples, fully coalesced 128B reads.
// relu before max (monotone-commutes) -> positive bits -> redux.max.u32.
// =======================================================================
__global__ void __launch_bounds__(256) pool_kernel(float* __restrict__ out) {
    __shared__ float sa[128], sc[128];
    const int tid = threadIdx.x;
    if (tid < 128) { sa[tid] = g_a3[tid]; sc[tid] = g_c3[tid]; }
    __syncthreads();
    const int wid = tid >> 5, lid = tid & 31;
    const int q = blockIdx.x * 8 + wid;
    const float* hbase = g_h3 + (size_t)q * NS + lid;
    const int b = q >> 9, sidx = q & 511;
    float* ob = out + (size_t)NB * 3 * NP + ((size_t)b * 128) * NP + sidx;
#pragma unroll 4
    for (int o = 0; o < 128; o++) {
        float v = hbase[(size_t)o * MROWS];
        float y = fmaxf(fmaf(sa[o], v, sc[o]), 0.0f);
        u32 m = rmaxu(__float_as_uint(y));
        if (lid == 0) ob[(size_t)o * NP] = __uint_as_float(m);
    }
}

// ---------------- launch ----------------
extern "C" void kernel_launch(void* const* d_in, const int* in_sizes, int n_in,
                              void* d_out, int out_size) {
    const float* xyz = (const float*)d_in[0];
    const float* pts = (const float*)d_in[1];
    const float* W0 = (const float*)d_in[2];
    const float* b0 = (const float*)d_in[3];
    const float* g0 = (const float*)d_in[4];
    const float* be0 = (const float*)d_in[5];
    const float* W1 = (const float*)d_in[6];
    const float* b1 = (const float*)d_in[7];
    const float* g1 = (const float*)d_in[8];
    const float* be1 = (const float*)d_in[9];
    const float* W2 = (const float*)d_in[10];
    const float* b2 = (const float*)d_in[11];
    const float* g2 = (const float*)d_in[12];
    const float* be2 = (const float*)d_in[13];
    float* out = (float*)d_out;

    void *h0, *h1, *h2, *h3, *a1, *c1, *a2, *c2, *a3, *c3, *part;
    cudaGetSymbolAddress(&h0, g_h0);
    cudaGetSymbolAddress(&h1, g_h1);
    cudaGetSymbolAddress(&h2, g_h2);
    cudaGetSymbolAddress(&h3, g_h3);
    cudaGetSymbolAddress(&a1, g_a1);
    cudaGetSymbolAddress(&c1, g_c1);
    cudaGetSymbolAddress(&a2, g_a2);
    cudaGetSymbolAddress(&c2, g_c2);
    cudaGetSymbolAddress(&a3, g_a3);
    cudaGetSymbolAddress(&c3, g_c3);
    cudaGetSymbolAddress(&part, g_part);

    const int fused_smem = 3 * NPTS * 4 + 16 * 8;  // cloud/keys + rw[2][8]
    cudaFuncSetAttribute(fused_fps_ball, cudaFuncAttributeMaxDynamicSharedMemorySize,
                         fused_smem);

    init_kernel<<<1, 32>>>();
    fused_fps_ball<<<NB + NB * NP, 256, fused_smem>>>(xyz, pts, out);

    mlp_kernel<9, false><<<dim3(MROWS / 256, 1), 256>>>(
        (const float*)h0, W0, b0, nullptr, nullptr, (float*)h1);
    coeffp_kernel<<<dim3(64, SEGS), 256>>>((const float*)h1, (float2*)part);
    comb_kernel<<<1, 128>>>((const float2*)part, g0, be0, (float*)a1, (float*)c1, 64);

    mlp_kernel<64, true><<<dim3(MROWS / 256, 1), 256>>>(
        (const float*)h1, W1, b1, (const float*)a1, (const float*)c1, (float*)h2);
    coeffp_kernel<<<dim3(64, SEGS), 256>>>((const float*)h2, (float2*)part);
    comb_kernel<<<1, 128>>>((const float2*)part, g1, be1, (float*)a2, (float*)c2, 64);

    mlp_kernel<64, true><<<dim3(MROWS / 256, 2), 256>>>(
        (const float*)h2, W2, b2, (const float*)a2, (const float*)c2, (float*)h3);
    coeffp_kernel<<<dim3(128, SEGS), 256>>>((const float*)h3, (float2*)part);
    comb_kernel<<<1, 128>>>((const float2*)part, g2, be2, (float*)a3, (float*)c3, 128);

    pool_kernel<<<NB * NP / 8, 256>>>(out);
}